// round 4
// baseline (speedup 1.0000x reference)
#include <cuda_runtime.h>
#include <cstdint>

typedef unsigned long long ull;

// ---------------- problem constants ----------------
#define HW_      65536      // 256*256 dense positions
#define CDIM     64
#define NKP      400
#define PMAX     2
#define NBLK     37         // m-chunk blocks
#define TILES_PER_BLK 14    // ceil(512/37)
#define TOTAL_M_TILES 512   // 65536/128
#define NTILES_N 4          // 4 * 100 = 400
#define N_TILE   100
#define M_TILE   128
#define TMAIN    320        // 32 tx (m) x 10 ty (n)
#define LOGIT_C  144.26950408889634f   // 100 * log2(e)

// ---------------- device scratch ----------------
__device__ float  g_invn[PMAX * HW_];          // (100*log2e) / ||src col||
__device__ float  g_tgt [PMAX * CDIM * NKP];   // normalized tgt desc
__device__ float4 g_part4[PMAX * NKP * NBLK];  // (S, X, Y, _) partials -- plain sums

// ---------------- packed f32x2 helpers ----------------
__device__ __forceinline__ void fma2acc(ull& d, ull a, ull b) {
    asm("fma.rn.f32x2 %0, %1, %2, %0;" : "+l"(d) : "l"(a), "l"(b));
}
__device__ __forceinline__ ull fma2(ull a, ull b, ull c) {
    ull d; asm("fma.rn.f32x2 %0, %1, %2, %3;" : "=l"(d) : "l"(a), "l"(b), "l"(c)); return d;
}
__device__ __forceinline__ ull add2(ull a, ull b) {
    ull d; asm("add.rn.f32x2 %0, %1, %2;" : "=l"(d) : "l"(a), "l"(b)); return d;
}
__device__ __forceinline__ ull mul2(ull a, ull b) {
    ull d; asm("mul.rn.f32x2 %0, %1, %2;" : "=l"(d) : "l"(a), "l"(b)); return d;
}
__device__ __forceinline__ ull dup2f(float v) {
    ull r; asm("mov.b64 %0, {%1, %1};" : "=l"(r) : "f"(v)); return r;
}
__device__ __forceinline__ ull pk2f(float a, float b) {
    ull r; asm("mov.b64 %0, {%1, %2};" : "=l"(r) : "f"(a), "f"(b)); return r;
}
__device__ __forceinline__ ull pk2u(unsigned a, unsigned b) {
    ull r; asm("mov.b64 %0, {%1, %2};" : "=l"(r) : "r"(a), "r"(b)); return r;
}
__device__ __forceinline__ float2 unpk(ull a) {
    float2 v; asm("mov.b64 {%0, %1}, %2;" : "=f"(v.x), "=f"(v.y) : "l"(a)); return v;
}
__device__ __forceinline__ void cp16(float* s, const float* g) {
    unsigned saddr = (unsigned)__cvta_generic_to_shared(s);
    asm volatile("cp.async.cg.shared.global [%0], [%1], 16;\n" :: "r"(saddr), "l"(g));
}

// packed exp2 (args <= ~0, may reach -290): magic round + deg-5 poly + int splice.
// ei clamped at -126 so underflowed terms become ~1e-38 (negligible vs ~1e-18 max weight).
struct E2C { ull mag, nmag, none, c5, c4, c3, c2, c1, one; };
__device__ __forceinline__ E2C make_e2c() {
    E2C C;
    C.mag  = dup2f(12582912.0f);
    C.nmag = dup2f(-12582912.0f);
    C.none = dup2f(-1.0f);
    C.c5   = dup2f(1.3333558146428443e-3f);
    C.c4   = dup2f(9.6181291076284772e-3f);
    C.c3   = dup2f(5.5504108664821580e-2f);
    C.c2   = dup2f(2.4022650695910071e-1f);
    C.c1   = dup2f(6.9314718055994531e-1f);
    C.one  = dup2f(1.0f);
    return C;
}
__device__ __forceinline__ ull exp2p(ull x, const E2C& C) {
    ull r = add2(x, C.mag);
    ull t = add2(r, C.nmag);
    ull f = fma2(t, C.none, x);        // f = x - rint(x), in [-0.5, 0.5]
    ull p = fma2(C.c5, f, C.c4);
    p = fma2(p, f, C.c3);
    p = fma2(p, f, C.c2);
    p = fma2(p, f, C.c1);
    p = fma2(p, f, C.one);
    unsigned lo = (unsigned)r, hi = (unsigned)(r >> 32);
    lo = (unsigned)max((int)lo, (int)0x4B3FFF82);   // clamp ei >= -126
    hi = (unsigned)max((int)hi, (int)0x4B3FFF82);
    lo = (lo + 0xB4C0007Fu) << 23;                  // ((ei+127)<<23)
    hi = (hi + 0xB4C0007Fu) << 23;
    return mul2(p, pk2u(lo, hi));
}

// ---------------- kernel 1: src column inverse norms (temp*log2e folded) ----------------
__global__ void k_src_norm(const float* __restrict__ dense, const int* __restrict__ src_ids) {
    int p = blockIdx.y;
    int m = blockIdx.x * blockDim.x + threadIdx.x;
    const float* base = dense + (size_t)src_ids[p] * CDIM * HW_ + m;
    float s = 0.f;
#pragma unroll
    for (int c = 0; c < CDIM; ++c) { float v = base[(size_t)c * HW_]; s = fmaf(v, v, s); }
    g_invn[p * HW_ + m] = LOGIT_C / fmaxf(sqrtf(s), 1e-12f);
}

// ---------------- kernel 2: normalize tgt desc, emit scores + ids ----------------
__global__ void k_tgt(const float* __restrict__ kdesc, const float* __restrict__ kscores,
                      const int* __restrict__ tgt_ids, const int* __restrict__ src_ids,
                      float* __restrict__ out, int out_size, int P) {
    int p = blockIdx.y;
    int n = blockIdx.x * blockDim.x + threadIdx.x;
    if (n < NKP) {
        const float* base = kdesc + (size_t)tgt_ids[p] * CDIM * NKP + n;
        float s = 0.f;
#pragma unroll
        for (int c = 0; c < CDIM; ++c) { float v = base[c * NKP]; s = fmaf(v, v, s); }
        float inv = 1.0f / fmaxf(sqrtf(s), 1e-12f);
#pragma unroll
        for (int c = 0; c < CDIM; ++c)
            g_tgt[((size_t)p * CDIM + c) * NKP + n] = base[c * NKP] * inv;
        int so = P * NKP * 2 + p * NKP + n;
        if (so < out_size) out[so] = kscores[tgt_ids[p] * NKP + n];
    }
    if (p == 0 && blockIdx.x == 0 && threadIdx.x == 0) {
        int base = P * NKP * 3;
        for (int pp = 0; pp < P; ++pp) {
            if (base + pp < out_size)     out[base + pp]     = (float)tgt_ids[pp];
            if (base + P + pp < out_size) out[base + P + pp] = (float)src_ids[pp];
        }
    }
}

// ---------------- kernel 3: GEMM + fixed-shift softmax accumulation ----------------
// grid (NBLK, NTILES_N, P), block 320 = 32 tx (m, 4 each) x 10 ty (n, 10 each)
// smem: B[2][64*128] | inv[2][128] | A2dup[64*200]
#define SMEM_FLOATS (2*64*128 + 2*128 + 64*200)
__global__ void __launch_bounds__(TMAIN, 1)
k_match(const float* __restrict__ dense, const int* __restrict__ src_ids) {
    extern __shared__ float smem[];
    float* B0  = smem;                     // 2 x 8192
    float* I0  = smem + 2 * 64 * 128;      // 2 x 128
    float* As2 = smem + 2 * 64 * 128 + 256; // 64 x 200 (A duplicated pairs)

    const int tid = threadIdx.x;
    const int tx  = tid & 31;
    const int ty  = tid >> 5;
    const int blk = blockIdx.x, ntile = blockIdx.y, p = blockIdx.z;

    const float* srcbase = dense + (size_t)src_ids[p] * CDIM * HW_;
    const float* invbase = g_invn + (size_t)p * HW_;
    const int nbase = ntile * N_TILE;

    // build duplicated A tile: As2[k][2n] = As2[k][2n+1] = that(k,n)
    for (int idx = tid; idx < CDIM * N_TILE; idx += TMAIN) {
        int k = idx / N_TILE, nl = idx - k * N_TILE;
        float v = g_tgt[((size_t)p * CDIM + k) * NKP + nbase + nl];
        As2[k * 200 + 2 * nl]     = v;
        As2[k * 200 + 2 * nl + 1] = v;
    }

    const int t0   = blk * TILES_PER_BLK;
    const int tcnt = min(TILES_PER_BLK, TOTAL_M_TILES - t0);

    ull S2[10], X2[10], Y2[10];
#pragma unroll
    for (int j = 0; j < 10; ++j) { S2[j] = 0ULL; X2[j] = 0ULL; Y2[j] = 0ULL; }

    const E2C C  = make_e2c();
    const ull CN = dup2f(-LOGIT_C);

    auto load_tile = [&](int t, int st) {
        int m0 = (t0 + t) * M_TILE;
        float* B = B0 + st * 8192;
        float* I = I0 + st * 128;
        for (int idx = tid; idx < 2048; idx += TMAIN) {
            int k = idx >> 5, seg = idx & 31;
            cp16(B + k * 128 + seg * 4, srcbase + (size_t)k * HW_ + m0 + seg * 4);
        }
        if (tid < 32) cp16(I + tid * 4, invbase + m0 + tid * 4);
        asm volatile("cp.async.commit_group;\n" ::);
    };

    load_tile(0, 0);

    for (int t = 0; t < tcnt; ++t) {
        const int st = t & 1;
        if (t + 1 < tcnt) {
            load_tile(t + 1, st ^ 1);
            asm volatile("cp.async.wait_group 1;\n" ::);
        } else {
            asm volatile("cp.async.wait_group 0;\n" ::);
        }
        __syncthreads();

        const float* B = B0 + st * 8192;
        ull acc[10][2];
#pragma unroll
        for (int j = 0; j < 10; ++j) { acc[j][0] = 0ULL; acc[j][1] = 0ULL; }

        const float* arow0 = As2 + ty * 20;
#pragma unroll 4
        for (int k = 0; k < CDIM; ++k) {
            ulonglong2 b = *(const ulonglong2*)(B + k * 128 + tx * 4);  // 4 m vals as 2 pairs
            const float* ar = arow0 + k * 200;
#pragma unroll
            for (int jp = 0; jp < 5; ++jp) {
                ulonglong2 av = *(const ulonglong2*)(ar + 4 * jp);      // (a,a),(a',a')
                fma2acc(acc[2 * jp][0],     av.x, b.x);
                fma2acc(acc[2 * jp][1],     av.x, b.y);
                fma2acc(acc[2 * jp + 1][0], av.y, b.x);
                fma2acc(acc[2 * jp + 1][1], av.y, b.y);
            }
        }

        // ---- packed epilogue: w = exp2(acc*inv - 100*log2e), accumulate S/X/Y ----
        const float* I = I0 + st * 128;
        ulonglong2 iv = *(const ulonglong2*)(I + tx * 4);   // inv-norm pairs over m
        const int m0v = (t0 + t) * M_TILE;
        const float xb = (float)(m0v & 255);
        const ull yf2 = dup2f((float)(m0v >> 8));
        const ull xo0 = pk2f(xb + (float)(tx * 4 + 0), xb + (float)(tx * 4 + 1));
        const ull xo1 = pk2f(xb + (float)(tx * 4 + 2), xb + (float)(tx * 4 + 3));

#pragma unroll
        for (int j = 0; j < 10; ++j) {
            ull w0 = exp2p(fma2(acc[j][0], iv.x, CN), C);
            ull w1 = exp2p(fma2(acc[j][1], iv.y, CN), C);
            ull stile = add2(w0, w1);
            S2[j] = add2(S2[j], stile);
            Y2[j] = fma2(stile, yf2, Y2[j]);
            X2[j] = fma2(w0, xo0, X2[j]);
            X2[j] = fma2(w1, xo1, X2[j]);
        }
        __syncthreads();
    }

    // ---- reduce across the 32 m-lanes (warp == one ty) : plain sums ----
#pragma unroll
    for (int j = 0; j < 10; ++j) {
        float2 sv = unpk(S2[j]); float s = sv.x + sv.y;
        float2 xv = unpk(X2[j]); float x = xv.x + xv.y;
        float2 yv = unpk(Y2[j]); float y = yv.x + yv.y;
#pragma unroll
        for (int off = 16; off; off >>= 1) {
            s += __shfl_xor_sync(0xffffffffu, s, off);
            x += __shfl_xor_sync(0xffffffffu, x, off);
            y += __shfl_xor_sync(0xffffffffu, y, off);
        }
        if (tx == 0)
            g_part4[((size_t)p * NKP + nbase + ty * 10 + j) * NBLK + blk] =
                make_float4(s, x, y, 0.f);
    }
}

// ---------------- kernel 4: combine partials (one warp per keypoint) ----------------
__global__ void k_combine(float* __restrict__ out, int P, int out_size) {
    int gw   = (blockIdx.x * blockDim.x + threadIdx.x) >> 5;
    int lane = threadIdx.x & 31;
    if (gw >= P * NKP) return;
    float S = 0.f, X = 0.f, Y = 0.f;
    for (int b = lane; b < NBLK; b += 32) {
        float4 v = g_part4[(size_t)gw * NBLK + b];
        S += v.x; X += v.y; Y += v.z;
    }
#pragma unroll
    for (int off = 16; off; off >>= 1) {
        S += __shfl_xor_sync(0xffffffffu, S, off);
        X += __shfl_xor_sync(0xffffffffu, X, off);
        Y += __shfl_xor_sync(0xffffffffu, Y, off);
    }
    if (lane == 0 && gw * 2 + 1 < out_size) {
        out[gw * 2 + 0] = X / S;
        out[gw * 2 + 1] = Y / S;
    }
}

// ---------------- launch ----------------
extern "C" void kernel_launch(void* const* d_in, const int* in_sizes, int n_in,
                              void* d_out, int out_size) {
    const float* kscores = (const float*)d_in[0];
    const float* kdesc   = (const float*)d_in[1];
    const float* dense   = (const float*)d_in[2];
    const int*   tgt_ids = (const int*)d_in[3];
    const int*   src_ids = (const int*)d_in[4];
    int P = in_sizes[3];
    if (P > PMAX) P = PMAX;
    float* out = (float*)d_out;

    k_src_norm<<<dim3(HW_ / 256, P), 256>>>(dense, src_ids);
    k_tgt<<<dim3(2, P), 256>>>(kdesc, kscores, tgt_ids, src_ids, out, out_size, P);

    const int smem_bytes = SMEM_FLOATS * sizeof(float);   // 117,760 B
    cudaFuncSetAttribute(k_match, cudaFuncAttributeMaxDynamicSharedMemorySize, smem_bytes);
    k_match<<<dim3(NBLK, NTILES_N, P), TMAIN, smem_bytes>>>(dense, src_ids);

    k_combine<<<(P * NKP * 32 + 255) / 256, 256>>>(out, P, out_size);
}

// round 6
// speedup vs baseline: 1.8999x; 1.8999x over previous
#include <cuda_runtime.h>
#include <cuda_bf16.h>
#include <cstdint>

// ---------------- problem constants ----------------
#define HW_      65536
#define CDIM     64
#define NKP      400
#define NKPAD    416        // 2 halves x 13 warps x 16
#define PMAX     2
#define NSTRIP   64
#define STRIP_M  1024
#define CHUNK_M  64
#define NCHUNK   16
#define NTHREADS 416        // 13 warps
#define LOGIT_C  144.26950408889634f   // 100 * log2(e)

// smem byte offsets: A rows have 144B stride (128B data + 16B pad -> conflict-free ldmatrix)
#define SA_HI  0
#define SA_LO  59904        // 416*144
#define SB     119808       // 2 bufs x (hi 9216 + lo 9216)
#define SSS    156672       // partial sum-of-squares [4][64]
#define SMEMSZ 157696

// ---------------- device scratch ----------------
__device__ float  g_tgt[PMAX * CDIM * NKP];       // normalized tgt desc
__device__ float4 g_part4[PMAX * NKPAD * NSTRIP]; // (S, X, Y, _) per kp per strip

// ---------------- helpers ----------------
__device__ __forceinline__ float ex2f(float x) {
    float y; asm("ex2.approx.ftz.f32 %0, %1;" : "=f"(y) : "f"(x)); return y;
}
// split (a,b) -> bf16 hi pair + bf16 residual pair
__device__ __forceinline__ void split2(float a, float b, uint32_t& h, uint32_t& l) {
    __nv_bfloat162 hh = __floats2bfloat162_rn(a, b);
    h = *reinterpret_cast<uint32_t*>(&hh);
    float fa = __uint_as_float(h << 16);
    float fb = __uint_as_float(h & 0xffff0000u);
    __nv_bfloat162 ll = __floats2bfloat162_rn(a - fa, b - fb);
    l = *reinterpret_cast<uint32_t*>(&ll);
}
__device__ __forceinline__ void ldsm4(uint32_t& r0, uint32_t& r1, uint32_t& r2, uint32_t& r3,
                                      uint32_t addr) {
    asm volatile("ldmatrix.sync.aligned.m8n8.x4.shared.b16 {%0,%1,%2,%3}, [%4];"
                 : "=r"(r0), "=r"(r1), "=r"(r2), "=r"(r3) : "r"(addr));
}
__device__ __forceinline__ void mma16816(float* c, const uint32_t* a, uint32_t b0, uint32_t b1) {
    asm volatile(
        "mma.sync.aligned.m16n8k16.row.col.f32.bf16.bf16.f32 "
        "{%0,%1,%2,%3}, {%4,%5,%6,%7}, {%8,%9}, {%0,%1,%2,%3};"
        : "+f"(c[0]), "+f"(c[1]), "+f"(c[2]), "+f"(c[3])
        : "r"(a[0]), "r"(a[1]), "r"(a[2]), "r"(a[3]), "r"(b0), "r"(b1));
}

// ---------------- kernel 1: normalize tgt desc, emit scores + ids ----------------
__global__ void k_tgt(const float* __restrict__ kdesc, const float* __restrict__ kscores,
                      const int* __restrict__ tgt_ids, const int* __restrict__ src_ids,
                      float* __restrict__ out, int out_size, int P) {
    int p = blockIdx.y;
    int n = blockIdx.x * blockDim.x + threadIdx.x;
    if (n < NKP) {
        const float* base = kdesc + (size_t)tgt_ids[p] * CDIM * NKP + n;
        float s = 0.f;
#pragma unroll
        for (int c = 0; c < CDIM; ++c) { float v = base[c * NKP]; s = fmaf(v, v, s); }
        float inv = 1.0f / fmaxf(sqrtf(s), 1e-12f);
#pragma unroll
        for (int c = 0; c < CDIM; ++c)
            g_tgt[((size_t)p * CDIM + c) * NKP + n] = base[c * NKP] * inv;
        int so = P * NKP * 2 + p * NKP + n;
        if (so < out_size) out[so] = kscores[tgt_ids[p] * NKP + n];
    }
    if (p == 0 && blockIdx.x == 0 && threadIdx.x == 0) {
        int base = P * NKP * 3;
        for (int pp = 0; pp < P; ++pp) {
            if (base + pp < out_size)     out[base + pp]     = (float)tgt_ids[pp];
            if (base + P + pp < out_size) out[base + P + pp] = (float)src_ids[pp];
        }
    }
}

// ---------------- kernel 2: bf16x3 mma.sync GEMM + fused softmax moments ----------------
// grid (64 strips, P). 13 warps; warp w handles kp rows [h*208 + w*16, +16) for h=0,1.
// All warps share each 64-m dense chunk (8 n8 frags). Inv-norm computed inline.
__global__ void __launch_bounds__(NTHREADS, 1)
k_match(const float* __restrict__ dense, const int* __restrict__ src_ids) {
    extern __shared__ char sm[];
    const uint32_t sb = (uint32_t)__cvta_generic_to_shared(sm);
    const int tid = threadIdx.x, w = tid >> 5, lane = tid & 31;
    const int strip = blockIdx.x, p = blockIdx.y;
    const size_t m_strip0 = (size_t)strip * STRIP_M;
    const float* srcb = dense + (size_t)src_ids[p] * CDIM * HW_;

    // ---- build A tile (416 kp x 64 k, bf16 hi/lo, K-major, 144B row stride) ----
    {
        const int kp = tid;
        const float* tb = g_tgt + (size_t)p * CDIM * NKP + kp;
        for (int kb = 0; kb < CDIM; kb += 8) {
            uint32_t hh[4], ll[4];
#pragma unroll
            for (int j = 0; j < 4; ++j) {
                float v0 = (kp < NKP) ? tb[(kb + 2 * j) * NKP]     : 0.f;
                float v1 = (kp < NKP) ? tb[(kb + 2 * j + 1) * NKP] : 0.f;
                split2(v0, v1, hh[j], ll[j]);
            }
            *(uint4*)(sm + SA_HI + kp * 144 + kb * 2) = make_uint4(hh[0], hh[1], hh[2], hh[3]);
            *(uint4*)(sm + SA_LO + kp * 144 + kb * 2) = make_uint4(ll[0], ll[1], ll[2], ll[3]);
        }
    }

    // ---- staging thread mapping (first 256 threads) ----
    const int mloc = tid & 63, kg = tid >> 6;
    float R[16];
    if (tid < 256) {
#pragma unroll
        for (int i = 0; i < 16; ++i)
            R[i] = srcb[(size_t)(kg * 16 + i) * HW_ + m_strip0 + mloc];
    }

    // persistent softmax moment accumulators (rows: [half][rowpart])
    float S[2][2]  = {{0.f,0.f},{0.f,0.f}};
    float XO[2][2] = {{0.f,0.f},{0.f,0.f}};
    float XB[2][2] = {{0.f,0.f},{0.f,0.f}};
    float Yc[2][2] = {{0.f,0.f},{0.f,0.f}};

    // ldmatrix lane-address pre-offsets
    const int preA = ((lane & 7) + ((lane >> 3) & 1) * 8) * 144 + ((lane >> 4) & 1) * 16;
    const int preB = ((lane & 7) + ((lane >> 4) & 1) * 8) * 144 + ((lane >> 3) & 1) * 16;
    const float xol = (float)((lane & 3) * 2);

    for (int t = 0; t < NCHUNK; ++t) {
        // ---- stage: sum-of-squares partials ----
        if (tid < 256) {
            float ss = 0.f;
#pragma unroll
            for (int i = 0; i < 16; ++i) ss = fmaf(R[i], R[i], ss);
            *(float*)(sm + SSS + (kg * 64 + mloc) * 4) = ss;
        }
        __syncthreads();
        // ---- stage: convert to bf16 hi/lo with LOGIT_C/norm folded; prefetch next ----
        if (tid < 256) {
            const float* ssp = (const float*)(sm + SSS);
            float tot = ssp[mloc] + ssp[64 + mloc] + ssp[128 + mloc] + ssp[192 + mloc];
            float inv = LOGIT_C / fmaxf(sqrtf(tot), 1e-12f);
            char* bh = sm + SB + (t & 1) * 18432;
            char* bl = bh + 9216;
#pragma unroll
            for (int blk = 0; blk < 2; ++blk) {
                uint32_t hh[4], ll[4];
#pragma unroll
                for (int j = 0; j < 4; ++j)
                    split2(R[blk * 8 + 2 * j] * inv, R[blk * 8 + 2 * j + 1] * inv, hh[j], ll[j]);
                int ko = (kg * 16 + blk * 8) * 2;
                *(uint4*)(bh + mloc * 144 + ko) = make_uint4(hh[0], hh[1], hh[2], hh[3]);
                *(uint4*)(bl + mloc * 144 + ko) = make_uint4(ll[0], ll[1], ll[2], ll[3]);
            }
            if (t + 1 < NCHUNK) {
#pragma unroll
                for (int i = 0; i < 16; ++i)
                    R[i] = srcb[(size_t)(kg * 16 + i) * HW_ + m_strip0 + (t + 1) * CHUNK_M + mloc];
            }
        }
        __syncthreads();

        // ---- compute chunk t ----
        const uint32_t Bh = sb + SB + (t & 1) * 18432;
        const uint32_t Bl = Bh + 9216;
        const int m0 = (int)m_strip0 + t * CHUNK_M;
        const float xb = (float)(m0 & 255), yv = (float)(m0 >> 8);

#pragma unroll
        for (int h = 0; h < 2; ++h) {
            const int arb = h * 208 + w * 16;
            const uint32_t Ah = sb + SA_HI + arb * 144 + preA;
            const uint32_t Al = sb + SA_LO + arb * 144 + preA;
            float c[8][4];
#pragma unroll
            for (int f = 0; f < 8; ++f) { c[f][0] = c[f][1] = c[f][2] = c[f][3] = 0.f; }

#pragma unroll
            for (int ks = 0; ks < 4; ++ks) {
                uint32_t ah[4], al[4];
                ldsm4(ah[0], ah[1], ah[2], ah[3], Ah + ks * 32);
                ldsm4(al[0], al[1], al[2], al[3], Al + ks * 32);
#pragma unroll
                for (int fp = 0; fp < 4; ++fp) {
                    uint32_t bh0, bh1, bh2, bh3, bl0, bl1, bl2, bl3;
                    ldsm4(bh0, bh1, bh2, bh3, Bh + fp * 2304 + preB + ks * 32);
                    ldsm4(bl0, bl1, bl2, bl3, Bl + fp * 2304 + preB + ks * 32);
                    mma16816(c[2 * fp],     ah, bh0, bh1);
                    mma16816(c[2 * fp],     ah, bl0, bl1);
                    mma16816(c[2 * fp],     al, bh0, bh1);
                    mma16816(c[2 * fp + 1], ah, bh2, bh3);
                    mma16816(c[2 * fp + 1], ah, bl2, bl3);
                    mma16816(c[2 * fp + 1], al, bh2, bh3);
                }
            }

            // ---- epilogue: w = 2^(logit - 100*log2e); rows = keypoints (in-register) ----
            float s0 = S[h][0], s1 = S[h][1];
            float x0 = XO[h][0], x1 = XO[h][1];
            const float sn0 = s0, sn1 = s1;
#pragma unroll
            for (int f = 0; f < 8; ++f) {
                float xo = xol + (float)(f * 8);
                float w0 = ex2f(c[f][0] - LOGIT_C);
                float w1 = ex2f(c[f][1] - LOGIT_C);
                float w2 = ex2f(c[f][2] - LOGIT_C);
                float w3 = ex2f(c[f][3] - LOGIT_C);
                s0 += w0 + w1;
                x0 = fmaf(w0, xo, x0); x0 = fmaf(w1, xo + 1.f, x0);
                s1 += w2 + w3;
                x1 = fmaf(w2, xo, x1); x1 = fmaf(w3, xo + 1.f, x1);
            }
            S[h][0] = s0; S[h][1] = s1; XO[h][0] = x0; XO[h][1] = x1;
            XB[h][0] = fmaf(xb, s0 - sn0, XB[h][0]);
            XB[h][1] = fmaf(xb, s1 - sn1, XB[h][1]);
            Yc[h][0] = fmaf(yv, s0 - sn0, Yc[h][0]);
            Yc[h][1] = fmaf(yv, s1 - sn1, Yc[h][1]);
        }
    }

    // ---- reduce over the 4 col-lanes (xor 1,2) and store partials ----
#pragma unroll
    for (int h = 0; h < 2; ++h)
#pragma unroll
        for (int rp = 0; rp < 2; ++rp) {
            float s = S[h][rp], x = XO[h][rp] + XB[h][rp], y = Yc[h][rp];
            s += __shfl_xor_sync(0xffffffffu, s, 1);
            x += __shfl_xor_sync(0xffffffffu, x, 1);
            y += __shfl_xor_sync(0xffffffffu, y, 1);
            s += __shfl_xor_sync(0xffffffffu, s, 2);
            x += __shfl_xor_sync(0xffffffffu, x, 2);
            y += __shfl_xor_sync(0xffffffffu, y, 2);
            if ((lane & 3) == 0) {
                int kp = h * 208 + w * 16 + (lane >> 2) + 8 * rp;
                g_part4[((size_t)p * NKPAD + kp) * NSTRIP + strip] = make_float4(s, x, y, 0.f);
            }
        }
}

// ---------------- kernel 3: combine partials (one warp per keypoint) ----------------
__global__ void k_combine(float* __restrict__ out, int P, int out_size) {
    int gw   = (blockIdx.x * blockDim.x + threadIdx.x) >> 5;
    int lane = threadIdx.x & 31;
    if (gw >= P * NKP) return;
    int p = gw / NKP, kp = gw - p * NKP;
    const float4* base = &g_part4[((size_t)p * NKPAD + kp) * NSTRIP];
    float S = 0.f, X = 0.f, Y = 0.f;
#pragma unroll
    for (int b = lane; b < NSTRIP; b += 32) {
        float4 v = base[b];
        S += v.x; X += v.y; Y += v.z;
    }
#pragma unroll
    for (int off = 16; off; off >>= 1) {
        S += __shfl_xor_sync(0xffffffffu, S, off);
        X += __shfl_xor_sync(0xffffffffu, X, off);
        Y += __shfl_xor_sync(0xffffffffu, Y, off);
    }
    if (lane == 0 && gw * 2 + 1 < out_size) {
        out[gw * 2 + 0] = X / S;
        out[gw * 2 + 1] = Y / S;
    }
}

// ---------------- launch ----------------
extern "C" void kernel_launch(void* const* d_in, const int* in_sizes, int n_in,
                              void* d_out, int out_size) {
    const float* kscores = (const float*)d_in[0];
    const float* kdesc   = (const float*)d_in[1];
    const float* dense   = (const float*)d_in[2];
    const int*   tgt_ids = (const int*)d_in[3];
    const int*   src_ids = (const int*)d_in[4];
    int P = in_sizes[3];
    if (P > PMAX) P = PMAX;
    float* out = (float*)d_out;

    k_tgt<<<dim3(2, P), 256>>>(kdesc, kscores, tgt_ids, src_ids, out, out_size, P);

    cudaFuncSetAttribute(k_match, cudaFuncAttributeMaxDynamicSharedMemorySize, SMEMSZ);
    k_match<<<dim3(NSTRIP, P), NTHREADS, SMEMSZ>>>(dense, src_ids);

    k_combine<<<(P * NKP * 32 + 255) / 256, 256>>>(out, P, out_size);
}

// round 8
// speedup vs baseline: 4.4458x; 2.3400x over previous
#include <cuda_runtime.h>
#include <cuda_fp16.h>
#include <cstdint>

// ---------------- problem constants ----------------
#define HW_      65536
#define CDIM     64
#define NKP      400
#define NKPAD    416        // 2 halves x 13 warps x 16
#define PMAX     2
#define NSTRIP   74         // x P=2 -> 148 CTAs = one full wave
#define NCHUNK_G 1024       // 65536 / 64
#define CHUNK_M  64
#define NTHREADS 416        // 13 warps
#define LOGIT_C  144.26950408889634f   // 100 * log2(e)

// smem byte offsets: rows have 144B stride (128B data + 16B pad, conflict-light ldmatrix)
#define SA_HI  0
#define SA_LO  59904        // 416*144
#define SB     119808       // 2 bufs x 9216 (single fp16 B)
#define SSS    138240       // partial sum-of-squares [4][64]
#define SMEMSZ 139264

// ---------------- device scratch ----------------
__device__ float4 g_part4[PMAX * NKPAD * NSTRIP]; // (S, X, Y, _) per kp per strip

// ---------------- helpers ----------------
__device__ __forceinline__ float ex2f(float x) {
    float y; asm("ex2.approx.ftz.f32 %0, %1;" : "=f"(y) : "f"(x)); return y;
}
// pack (a,b) -> fp16x2
__device__ __forceinline__ uint32_t pkh2(float a, float b) {
    __half2 h = __floats2half2_rn(a, b);
    return *reinterpret_cast<uint32_t*>(&h);
}
// split (a,b) -> fp16 hi pair + fp16 residual pair
__device__ __forceinline__ void split2h(float a, float b, uint32_t& h, uint32_t& l) {
    __half2 hh = __floats2half2_rn(a, b);
    h = *reinterpret_cast<uint32_t*>(&hh);
    float2 hf = __half22float2(hh);
    __half2 ll = __floats2half2_rn(a - hf.x, b - hf.y);
    l = *reinterpret_cast<uint32_t*>(&ll);
}
__device__ __forceinline__ void ldsm4(uint32_t& r0, uint32_t& r1, uint32_t& r2, uint32_t& r3,
                                      uint32_t addr) {
    asm volatile("ldmatrix.sync.aligned.m8n8.x4.shared.b16 {%0,%1,%2,%3}, [%4];"
                 : "=r"(r0), "=r"(r1), "=r"(r2), "=r"(r3) : "r"(addr));
}
__device__ __forceinline__ void mma16816(float* c, const uint32_t* a, uint32_t b0, uint32_t b1) {
    asm volatile(
        "mma.sync.aligned.m16n8k16.row.col.f32.f16.f16.f32 "
        "{%0,%1,%2,%3}, {%4,%5,%6,%7}, {%8,%9}, {%0,%1,%2,%3};"
        : "+f"(c[0]), "+f"(c[1]), "+f"(c[2]), "+f"(c[3])
        : "r"(a[0]), "r"(a[1]), "r"(a[2]), "r"(a[3]), "r"(b0), "r"(b1));
}

// ---------------- kernel 1: fp16 mma GEMM + fused softmax moments ----------------
// grid (NSTRIP, P). 13 warps; frag (h,w): kp rows [h*208 + w*16, +16); (h=1,w=12) skipped.
// A (tgt, normalized inline, x LOGIT_C, hi/lo fp16) built once; B (dense, 1/norm inline,
// single fp16) double-buffered per 64-m chunk.
__global__ void __launch_bounds__(NTHREADS, 1)
k_match(const float* __restrict__ dense, const float* __restrict__ kdesc,
        const int* __restrict__ tgt_ids, const int* __restrict__ src_ids) {
    extern __shared__ char sm[];
    const uint32_t sb = (uint32_t)__cvta_generic_to_shared(sm);
    const int tid = threadIdx.x, w = tid >> 5, lane = tid & 31;
    const int strip = blockIdx.x, p = blockIdx.y;
    const int c0 = (strip * NCHUNK_G) / NSTRIP;
    const int c1 = ((strip + 1) * NCHUNK_G) / NSTRIP;
    const float* srcb = dense + (size_t)src_ids[p] * CDIM * HW_;

    // ---- build A tile: normalize tgt inline, fold LOGIT_C, split fp16 hi/lo ----
    {
        const int kp = tid;
        float v[CDIM];
        float ss = 0.f;
        if (kp < NKP) {
            const float* tb = kdesc + (size_t)tgt_ids[p] * CDIM * NKP + kp;
#pragma unroll
            for (int c = 0; c < CDIM; ++c) { v[c] = tb[c * NKP]; ss = fmaf(v[c], v[c], ss); }
        } else {
#pragma unroll
            for (int c = 0; c < CDIM; ++c) v[c] = 0.f;
            ss = 1.f;
        }
        float inv = LOGIT_C / fmaxf(sqrtf(ss), 1e-12f);
        for (int kb = 0; kb < CDIM; kb += 8) {
            uint32_t hh[4], ll[4];
#pragma unroll
            for (int j = 0; j < 4; ++j)
                split2h(v[kb + 2 * j] * inv, v[kb + 2 * j + 1] * inv, hh[j], ll[j]);
            *(uint4*)(sm + SA_HI + kp * 144 + kb * 2) = make_uint4(hh[0], hh[1], hh[2], hh[3]);
            *(uint4*)(sm + SA_LO + kp * 144 + kb * 2) = make_uint4(ll[0], ll[1], ll[2], ll[3]);
        }
    }

    // ---- staging thread mapping (first 256 threads) ----
    const int mloc = tid & 63, kg = tid >> 6;
    float R[16];
    if (tid < 256) {
#pragma unroll
        for (int i = 0; i < 16; ++i)
            R[i] = srcb[(size_t)(kg * 16 + i) * HW_ + (size_t)c0 * CHUNK_M + mloc];
    }
    __syncthreads();

    // persistent softmax moment accumulators [half][rowpart]
    float S[2][2]  = {{0.f,0.f},{0.f,0.f}};
    float XO[2][2] = {{0.f,0.f},{0.f,0.f}};
    float XB[2][2] = {{0.f,0.f},{0.f,0.f}};
    float Yc[2][2] = {{0.f,0.f},{0.f,0.f}};

    const int preA = ((lane & 7) + ((lane >> 3) & 1) * 8) * 144 + ((lane >> 4) & 1) * 16;
    const int preB = ((lane & 7) + ((lane >> 4) & 1) * 8) * 144 + ((lane >> 3) & 1) * 16;
    const float xol = (float)((lane & 3) * 2);

    for (int t = c0; t < c1; ++t) {
        // ---- stage: sum-of-squares partials ----
        if (tid < 256) {
            float ss = 0.f;
#pragma unroll
            for (int i = 0; i < 16; ++i) ss = fmaf(R[i], R[i], ss);
            *(float*)(sm + SSS + (kg * 64 + mloc) * 4) = ss;
        }
        __syncthreads();
        // ---- stage: fp16 convert with 1/norm folded; prefetch next chunk ----
        if (tid < 256) {
            const float* ssp = (const float*)(sm + SSS);
            float tot = ssp[mloc] + ssp[64 + mloc] + ssp[128 + mloc] + ssp[192 + mloc];
            float inv = 1.0f / fmaxf(sqrtf(tot), 1e-12f);
            char* bb = sm + SB + (t & 1) * 9216;
            uint32_t q[8];
#pragma unroll
            for (int j = 0; j < 8; ++j)
                q[j] = pkh2(R[2 * j] * inv, R[2 * j + 1] * inv);
            *(uint4*)(bb + mloc * 144 + kg * 32)      = make_uint4(q[0], q[1], q[2], q[3]);
            *(uint4*)(bb + mloc * 144 + kg * 32 + 16) = make_uint4(q[4], q[5], q[6], q[7]);
            if (t + 1 < c1) {
#pragma unroll
                for (int i = 0; i < 16; ++i)
                    R[i] = srcb[(size_t)(kg * 16 + i) * HW_ + (size_t)(t + 1) * CHUNK_M + mloc];
            }
        }
        __syncthreads();

        // ---- compute chunk t ----
        const uint32_t Bb = sb + SB + (t & 1) * 9216;
        const int m0 = t * CHUNK_M;
        const float xb = (float)(m0 & 255), yv = (float)(m0 >> 8);

#pragma unroll
        for (int h = 0; h < 2; ++h) {
            if (h == 1 && w == 12) continue;   // kp 400-415 = padding, skip
            const int arb = h * 208 + w * 16;
            const uint32_t Ah = sb + SA_HI + arb * 144 + preA;
            const uint32_t Al = sb + SA_LO + arb * 144 + preA;
            float c[8][4];
#pragma unroll
            for (int f = 0; f < 8; ++f) { c[f][0] = c[f][1] = c[f][2] = c[f][3] = 0.f; }

#pragma unroll
            for (int ks = 0; ks < 4; ++ks) {
                uint32_t ah[4], al[4];
                ldsm4(ah[0], ah[1], ah[2], ah[3], Ah + ks * 32);
                ldsm4(al[0], al[1], al[2], al[3], Al + ks * 32);
#pragma unroll
                for (int fp = 0; fp < 4; ++fp) {
                    uint32_t b0, b1, b2, b3;
                    ldsm4(b0, b1, b2, b3, Bb + fp * 2304 + preB + ks * 32);
                    mma16816(c[2 * fp],     ah, b0, b1);
                    mma16816(c[2 * fp],     al, b0, b1);
                    mma16816(c[2 * fp + 1], ah, b2, b3);
                    mma16816(c[2 * fp + 1], al, b2, b3);
                }
            }

            // ---- epilogue: w = 2^(logit - 100*log2e); rows = keypoints ----
            float s0 = S[h][0], s1 = S[h][1];
            float x0 = XO[h][0], x1 = XO[h][1];
            const float sn0 = s0, sn1 = s1;
#pragma unroll
            for (int f = 0; f < 8; ++f) {
                float xo = xol + (float)(f * 8);
                float w0 = ex2f(c[f][0] - LOGIT_C);
                float w1 = ex2f(c[f][1] - LOGIT_C);
                float w2 = ex2f(c[f][2] - LOGIT_C);
                float w3 = ex2f(c[f][3] - LOGIT_C);
                s0 += w0 + w1;
                x0 = fmaf(w0, xo, x0); x0 = fmaf(w1, xo + 1.f, x0);
                s1 += w2 + w3;
                x1 = fmaf(w2, xo, x1); x1 = fmaf(w3, xo + 1.f, x1);
            }
            S[h][0] = s0; S[h][1] = s1; XO[h][0] = x0; XO[h][1] = x1;
            XB[h][0] = fmaf(xb, s0 - sn0, XB[h][0]);
            XB[h][1] = fmaf(xb, s1 - sn1, XB[h][1]);
            Yc[h][0] = fmaf(yv, s0 - sn0, Yc[h][0]);
            Yc[h][1] = fmaf(yv, s1 - sn1, Yc[h][1]);
        }
    }

    // ---- reduce over the 4 col-lanes and store partials ----
#pragma unroll
    for (int h = 0; h < 2; ++h) {
        if (h == 1 && w == 12) continue;
#pragma unroll
        for (int rp = 0; rp < 2; ++rp) {
            float s = S[h][rp], x = XO[h][rp] + XB[h][rp], y = Yc[h][rp];
            s += __shfl_xor_sync(0xffffffffu, s, 1);
            x += __shfl_xor_sync(0xffffffffu, x, 1);
            y += __shfl_xor_sync(0xffffffffu, y, 1);
            s += __shfl_xor_sync(0xffffffffu, s, 2);
            x += __shfl_xor_sync(0xffffffffu, x, 2);
            y += __shfl_xor_sync(0xffffffffu, y, 2);
            if ((lane & 3) == 0) {
                int kp = h * 208 + w * 16 + (lane >> 2) + 8 * rp;
                g_part4[((size_t)p * NKPAD + kp) * NSTRIP + strip] = make_float4(s, x, y, 0.f);
            }
        }
    }
}

// ---------------- kernel 2: combine partials + emit scores/ids ----------------
__global__ void k_combine(const float* __restrict__ kscores,
                          const int* __restrict__ tgt_ids, const int* __restrict__ src_ids,
                          float* __restrict__ out, int P, int out_size) {
    int gw   = (blockIdx.x * blockDim.x + threadIdx.x) >> 5;
    int lane = threadIdx.x & 31;
    if (blockIdx.x == 0 && threadIdx.x == 0) {
        int base = P * NKP * 3;
        for (int pp = 0; pp < P; ++pp) {
            if (base + pp < out_size)     out[base + pp]     = (float)tgt_ids[pp];
            if (base + P + pp < out_size) out[base + P + pp] = (float)src_ids[pp];
        }
    }
    if (gw >= P * NKP) return;
    int p = gw / NKP, kp = gw - p * NKP;
    const float4* base = &g_part4[((size_t)p * NKPAD + kp) * NSTRIP];
    float S = 0.f, X = 0.f, Y = 0.f;
    for (int b = lane; b < NSTRIP; b += 32) {
        float4 v = base[b];
        S += v.x; X += v.y; Y += v.z;
    }
#pragma unroll
    for (int off = 16; off; off >>= 1) {
        S += __shfl_xor_sync(0xffffffffu, S, off);
        X += __shfl_xor_sync(0xffffffffu, X, off);
        Y += __shfl_xor_sync(0xffffffffu, Y, off);
    }
    if (lane == 0) {
        if (gw * 2 + 1 < out_size) {
            out[gw * 2 + 0] = X / S;
            out[gw * 2 + 1] = Y / S;
        }
        int so = P * NKP * 2 + p * NKP + kp;
        if (so < out_size) out[so] = kscores[tgt_ids[p] * NKP + kp];
    }
}

// ---------------- launch ----------------
extern "C" void kernel_launch(void* const* d_in, const int* in_sizes, int n_in,
                              void* d_out, int out_size) {
    const float* kscores = (const float*)d_in[0];
    const float* kdesc   = (const float*)d_in[1];
    const float* dense   = (const float*)d_in[2];
    const int*   tgt_ids = (const int*)d_in[3];
    const int*   src_ids = (const int*)d_in[4];
    int P = in_sizes[3];
    if (P > PMAX) P = PMAX;
    float* out = (float*)d_out;

    cudaFuncSetAttribute(k_match, cudaFuncAttributeMaxDynamicSharedMemorySize, SMEMSZ);
    k_match<<<dim3(NSTRIP, P), NTHREADS, SMEMSZ>>>(dense, kdesc, tgt_ids, src_ids);

    k_combine<<<(P * NKP * 32 + 255) / 256, 256>>>(kscores, tgt_ids, src_ids, out, P, out_size);
}

// round 9
// speedup vs baseline: 4.5992x; 1.0345x over previous
#include <cuda_runtime.h>
#include <cuda_fp16.h>
#include <cstdint>

// ---------------- problem constants ----------------
#define HW_      65536
#define CDIM     64
#define NKP      400
#define NKPAD    416        // 2 halves x 13 warps x 16
#define PMAX     2
#define NSTRIP   74         // x P=2 -> 148 CTAs = one full wave
#define NCHUNK_G 1024       // 65536 / 64
#define CHUNK_M  64
#define NTHREADS 416        // 13 warps
#define LOGIT_C  144.26950408889634f   // 100 * log2(e)

// smem byte offsets: rows have 144B stride (128B data + 16B pad, conflict-free ldmatrix)
#define SA_HI  0
#define SA_LO  59904        // 416*144
#define SB     119808       // 2 bufs x 9216 (single fp16 B)
#define SN     138240       // inv-norms for whole strip (<= 896 floats)
#define SMEMSZ 141824

// ---------------- device scratch ----------------
__device__ float4 g_part4[PMAX * NKPAD * NSTRIP]; // (S, X, Y, _) per kp per strip

// ---------------- helpers ----------------
__device__ __forceinline__ float ex2f(float x) {
    float y; asm("ex2.approx.ftz.f32 %0, %1;" : "=f"(y) : "f"(x)); return y;
}
__device__ __forceinline__ uint32_t pkh2(float a, float b) {
    __half2 h = __floats2half2_rn(a, b);
    return *reinterpret_cast<uint32_t*>(&h);
}
// split (a,b) -> fp16 hi pair + fp16 residual pair
__device__ __forceinline__ void split2h(float a, float b, uint32_t& h, uint32_t& l) {
    __half2 hh = __floats2half2_rn(a, b);
    h = *reinterpret_cast<uint32_t*>(&hh);
    float2 hf = __half22float2(hh);
    __half2 ll = __floats2half2_rn(a - hf.x, b - hf.y);
    l = *reinterpret_cast<uint32_t*>(&ll);
}
__device__ __forceinline__ void ldsm4(uint32_t& r0, uint32_t& r1, uint32_t& r2, uint32_t& r3,
                                      uint32_t addr) {
    asm volatile("ldmatrix.sync.aligned.m8n8.x4.shared.b16 {%0,%1,%2,%3}, [%4];"
                 : "=r"(r0), "=r"(r1), "=r"(r2), "=r"(r3) : "r"(addr));
}
__device__ __forceinline__ void mma16816(float* c, const uint32_t* a, uint32_t b0, uint32_t b1) {
    asm volatile(
        "mma.sync.aligned.m16n8k16.row.col.f32.f16.f16.f32 "
        "{%0,%1,%2,%3}, {%4,%5,%6,%7}, {%8,%9}, {%0,%1,%2,%3};"
        : "+f"(c[0]), "+f"(c[1]), "+f"(c[2]), "+f"(c[3])
        : "r"(a[0]), "r"(a[1]), "r"(a[2]), "r"(a[3]), "r"(b0), "r"(b1));
}

// ---------------- kernel 1: fp16 mma GEMM + fused softmax moments ----------------
// grid (NSTRIP, P). 13 warps; frag (h,w): kp rows [h*208 + w*16, +16); (h=1,w=12) skipped.
// Pipeline: one __syncthreads per chunk; staging warps convert chunk t+1 while all
// warps compute chunk t. Inv-norms precomputed for the whole strip in the prologue.
__global__ void __launch_bounds__(NTHREADS, 1)
k_match(const float* __restrict__ dense, const float* __restrict__ kdesc,
        const int* __restrict__ tgt_ids, const int* __restrict__ src_ids) {
    extern __shared__ char sm[];
    const uint32_t sb = (uint32_t)__cvta_generic_to_shared(sm);
    float* SNp = (float*)(sm + SN);
    const int tid = threadIdx.x, w = tid >> 5, lane = tid & 31;
    const int strip = blockIdx.x, p = blockIdx.y;
    const int c0 = (strip * NCHUNK_G) / NSTRIP;
    const int c1 = ((strip + 1) * NCHUNK_G) / NSTRIP;
    const float* srcb = dense + (size_t)src_ids[p] * CDIM * HW_;

    // ---- staging thread mapping (first 256 threads) + early LDG of chunk c0 ----
    const int mloc = tid & 63, kg = tid >> 6;
    float R[16];
    if (tid < 256) {
#pragma unroll
        for (int i = 0; i < 16; ++i)
            R[i] = srcb[(size_t)(kg * 16 + i) * HW_ + (size_t)c0 * CHUNK_M + mloc];
    }

    // ---- build A tile: normalize tgt inline, fold LOGIT_C, split fp16 hi/lo ----
    {
        const int kp = tid;
        float v[CDIM];
        float ss = 0.f;
        if (kp < NKP) {
            const float* tb = kdesc + (size_t)tgt_ids[p] * CDIM * NKP + kp;
#pragma unroll
            for (int c = 0; c < CDIM; ++c) { v[c] = tb[c * NKP]; ss = fmaf(v[c], v[c], ss); }
        } else {
#pragma unroll
            for (int c = 0; c < CDIM; ++c) v[c] = 0.f;
            ss = 1.f;
        }
        float inv = LOGIT_C / fmaxf(sqrtf(ss), 1e-12f);
        for (int kb = 0; kb < CDIM; kb += 8) {
            uint32_t hh[4], ll[4];
#pragma unroll
            for (int j = 0; j < 4; ++j)
                split2h(v[kb + 2 * j] * inv, v[kb + 2 * j + 1] * inv, hh[j], ll[j]);
            *(uint4*)(sm + SA_HI + kp * 144 + kb * 2) = make_uint4(hh[0], hh[1], hh[2], hh[3]);
            *(uint4*)(sm + SA_LO + kp * 144 + kb * 2) = make_uint4(ll[0], ll[1], ll[2], ll[3]);
        }
    }

    // ---- precompute inv-norms for the whole strip (coalesced across threads) ----
    {
        const int nm = (c1 - c0) * CHUNK_M;
        for (int idx = tid; idx < nm; idx += NTHREADS) {
            size_t m = (size_t)c0 * CHUNK_M + idx;
            float ss = 0.f;
#pragma unroll
            for (int k = 0; k < CDIM; ++k) {
                float v = srcb[(size_t)k * HW_ + m];
                ss = fmaf(v, v, ss);
            }
            SNp[idx] = 1.0f / fmaxf(sqrtf(ss), 1e-12f);
        }
    }
    __syncthreads();   // A + SN ready

    // ---- prologue: convert chunk c0, prefetch chunk c0+1 ----
    if (tid < 256) {
        float inv = SNp[mloc];                 // chunk c0, local index 0
        char* bb = sm + SB + (c0 & 1) * 9216;
        uint32_t q[8];
#pragma unroll
        for (int j = 0; j < 8; ++j) q[j] = pkh2(R[2 * j] * inv, R[2 * j + 1] * inv);
        *(uint4*)(bb + mloc * 144 + kg * 32)      = make_uint4(q[0], q[1], q[2], q[3]);
        *(uint4*)(bb + mloc * 144 + kg * 32 + 16) = make_uint4(q[4], q[5], q[6], q[7]);
        if (c0 + 1 < c1) {
#pragma unroll
            for (int i = 0; i < 16; ++i)
                R[i] = srcb[(size_t)(kg * 16 + i) * HW_ + (size_t)(c0 + 1) * CHUNK_M + mloc];
        }
    }

    // persistent softmax moment accumulators [half][rowpart]
    float S[2][2]  = {{0.f,0.f},{0.f,0.f}};
    float XO[2][2] = {{0.f,0.f},{0.f,0.f}};
    float XB[2][2] = {{0.f,0.f},{0.f,0.f}};
    float Yc[2][2] = {{0.f,0.f},{0.f,0.f}};

    const int preA = ((lane & 7) + ((lane >> 3) & 1) * 8) * 144 + ((lane >> 4) & 1) * 16;
    const int preB = ((lane & 7) + ((lane >> 4) & 1) * 8) * 144 + ((lane >> 3) & 1) * 16;
    const float xol = (float)((lane & 3) * 2);

    for (int t = c0; t < c1; ++t) {
        __syncthreads();   // buf[t&1] ready; previous readers of buf[(t+1)&1] done

        // ---- compute chunk t ----
        const uint32_t Bb = sb + SB + (t & 1) * 9216;
        const int m0 = t * CHUNK_M;
        const float xb = (float)(m0 & 255), yv = (float)(m0 >> 8);

#pragma unroll
        for (int h = 0; h < 2; ++h) {
            if (h == 1 && w == 12) continue;   // kp 400-415 = padding, skip
            const int arb = h * 208 + w * 16;
            const uint32_t Ah = sb + SA_HI + arb * 144 + preA;
            const uint32_t Al = sb + SA_LO + arb * 144 + preA;
            float c[8][4];
#pragma unroll
            for (int f = 0; f < 8; ++f) {      // fold -100*log2e into accumulator init
                c[f][0] = c[f][1] = c[f][2] = c[f][3] = -LOGIT_C;
            }

#pragma unroll
            for (int ks = 0; ks < 4; ++ks) {
                uint32_t ah[4], al[4];
                ldsm4(ah[0], ah[1], ah[2], ah[3], Ah + ks * 32);
                ldsm4(al[0], al[1], al[2], al[3], Al + ks * 32);
#pragma unroll
                for (int fp = 0; fp < 4; ++fp) {
                    uint32_t b0, b1, b2, b3;
                    ldsm4(b0, b1, b2, b3, Bb + fp * 2304 + preB + ks * 32);
                    mma16816(c[2 * fp],     ah, b0, b1);
                    mma16816(c[2 * fp],     al, b0, b1);
                    mma16816(c[2 * fp + 1], ah, b2, b3);
                    mma16816(c[2 * fp + 1], al, b2, b3);
                }
            }

            // ---- epilogue: w = 2^c (shift already folded); rows = keypoints ----
            float s0 = S[h][0], s1 = S[h][1];
            float x0 = XO[h][0], x1 = XO[h][1];
            const float sn0 = s0, sn1 = s1;
#pragma unroll
            for (int f = 0; f < 8; ++f) {
                float xo = xol + (float)(f * 8);
                float w0 = ex2f(c[f][0]);
                float w1 = ex2f(c[f][1]);
                float w2 = ex2f(c[f][2]);
                float w3 = ex2f(c[f][3]);
                s0 += w0 + w1;
                x0 = fmaf(w0, xo, x0); x0 = fmaf(w1, xo + 1.f, x0);
                s1 += w2 + w3;
                x1 = fmaf(w2, xo, x1); x1 = fmaf(w3, xo + 1.f, x1);
            }
            S[h][0] = s0; S[h][1] = s1; XO[h][0] = x0; XO[h][1] = x1;
            XB[h][0] = fmaf(xb, s0 - sn0, XB[h][0]);
            XB[h][1] = fmaf(xb, s1 - sn1, XB[h][1]);
            Yc[h][0] = fmaf(yv, s0 - sn0, Yc[h][0]);
            Yc[h][1] = fmaf(yv, s1 - sn1, Yc[h][1]);
        }

        // ---- staging (overlapped with compute): convert chunk t+1, prefetch t+2 ----
        if (tid < 256 && t + 1 < c1) {
            float inv = SNp[(t + 1 - c0) * CHUNK_M + mloc];
            char* bb = sm + SB + ((t + 1) & 1) * 9216;
            uint32_t q[8];
#pragma unroll
            for (int j = 0; j < 8; ++j) q[j] = pkh2(R[2 * j] * inv, R[2 * j + 1] * inv);
            *(uint4*)(bb + mloc * 144 + kg * 32)      = make_uint4(q[0], q[1], q[2], q[3]);
            *(uint4*)(bb + mloc * 144 + kg * 32 + 16) = make_uint4(q[4], q[5], q[6], q[7]);
            if (t + 2 < c1) {
#pragma unroll
                for (int i = 0; i < 16; ++i)
                    R[i] = srcb[(size_t)(kg * 16 + i) * HW_ + (size_t)(t + 2) * CHUNK_M + mloc];
            }
        }
    }

    // ---- reduce over the 4 col-lanes and store partials ----
#pragma unroll
    for (int h = 0; h < 2; ++h) {
        if (h == 1 && w == 12) continue;
#pragma unroll
        for (int rp = 0; rp < 2; ++rp) {
            float s = S[h][rp], x = XO[h][rp] + XB[h][rp], y = Yc[h][rp];
            s += __shfl_xor_sync(0xffffffffu, s, 1);
            x += __shfl_xor_sync(0xffffffffu, x, 1);
            y += __shfl_xor_sync(0xffffffffu, y, 1);
            s += __shfl_xor_sync(0xffffffffu, s, 2);
            x += __shfl_xor_sync(0xffffffffu, x, 2);
            y += __shfl_xor_sync(0xffffffffu, y, 2);
            if ((lane & 3) == 0) {
                int kp = h * 208 + w * 16 + (lane >> 2) + 8 * rp;
                g_part4[((size_t)p * NKPAD + kp) * NSTRIP + strip] = make_float4(s, x, y, 0.f);
            }
        }
    }
}

// ---------------- kernel 2: combine partials + emit scores/ids (1 warp per kp) ----------------
__global__ void k_combine(const float* __restrict__ kscores,
                          const int* __restrict__ tgt_ids, const int* __restrict__ src_ids,
                          float* __restrict__ out, int P, int out_size) {
    int gw   = blockIdx.x;                 // one 32-thread block per keypoint
    int lane = threadIdx.x;
    if (gw == 0 && lane == 0) {
        int base = P * NKP * 3;
        for (int pp = 0; pp < P; ++pp) {
            if (base + pp < out_size)     out[base + pp]     = (float)tgt_ids[pp];
            if (base + P + pp < out_size) out[base + P + pp] = (float)src_ids[pp];
        }
    }
    if (gw >= P * NKP) return;
    int p = gw / NKP, kp = gw - p * NKP;
    const float4* base = &g_part4[((size_t)p * NKPAD + kp) * NSTRIP];
    float4 v0 = base[lane];
    float4 v1 = (lane + 32 < NSTRIP) ? base[lane + 32] : make_float4(0.f, 0.f, 0.f, 0.f);
    float4 v2 = (lane + 64 < NSTRIP) ? base[lane + 64] : make_float4(0.f, 0.f, 0.f, 0.f);
    float S = v0.x + v1.x + v2.x;
    float X = v0.y + v1.y + v2.y;
    float Y = v0.z + v1.z + v2.z;
#pragma unroll
    for (int off = 16; off; off >>= 1) {
        S += __shfl_xor_sync(0xffffffffu, S, off);
        X += __shfl_xor_sync(0xffffffffu, X, off);
        Y += __shfl_xor_sync(0xffffffffu, Y, off);
    }
    if (lane == 0) {
        if (gw * 2 + 1 < out_size) {
            out[gw * 2 + 0] = X / S;
            out[gw * 2 + 1] = Y / S;
        }
        int so = P * NKP * 2 + p * NKP + kp;
        if (so < out_size) out[so] = kscores[tgt_ids[p] * NKP + kp];
    }
}

// ---------------- launch ----------------
extern "C" void kernel_launch(void* const* d_in, const int* in_sizes, int n_in,
                              void* d_out, int out_size) {
    const float* kscores = (const float*)d_in[0];
    const float* kdesc   = (const float*)d_in[1];
    const float* dense   = (const float*)d_in[2];
    const int*   tgt_ids = (const int*)d_in[3];
    const int*   src_ids = (const int*)d_in[4];
    int P = in_sizes[3];
    if (P > PMAX) P = PMAX;
    float* out = (float*)d_out;

    cudaFuncSetAttribute(k_match, cudaFuncAttributeMaxDynamicSharedMemorySize, SMEMSZ);
    k_match<<<dim3(NSTRIP, P), NTHREADS, SMEMSZ>>>(dense, kdesc, tgt_ids, src_ids);

    k_combine<<<P * NKP, 32>>>(kscores, tgt_ids, src_ids, out, P, out_size);
}

// round 10
// speedup vs baseline: 6.0322x; 1.3116x over previous
#include <cuda_runtime.h>
#include <cuda_fp16.h>
#include <cstdint>

// ---------------- problem constants ----------------
#define HW_      65536
#define CDIM     64
#define NKP      400        // = 25 frags x 16, exact
#define NFRAG    25
#define PMAX     2
#define NSTRIP   74         // x P=2 -> 148 CTAs = one full wave
#define NCHUNK_G 1024       // 65536 / 64
#define CHUNK_M  64
#define NTHREADS 512        // 16 warps
#define LOGIT_C  144.26950408889634f   // 100 * log2(e)

// smem: A rows 144B stride (128B fp16 data + 16B pad); B bufs 64 rows x 144B
#define SA     0
#define SB     57600        // 2 bufs x 9216
#define SMEMSZ 76032

// ---------------- device scratch ----------------
__device__ float4 g_part4[PMAX * NKP * NSTRIP]; // (S, X, Y, _) per kp per strip

// ---------------- helpers ----------------
__device__ __forceinline__ float ex2f(float x) {
    float y; asm("ex2.approx.ftz.f32 %0, %1;" : "=f"(y) : "f"(x)); return y;
}
__device__ __forceinline__ uint32_t pkh2(float a, float b) {
    __half2 h = __floats2half2_rn(a, b);
    return *reinterpret_cast<uint32_t*>(&h);
}
__device__ __forceinline__ void ldsm4(uint32_t& r0, uint32_t& r1, uint32_t& r2, uint32_t& r3,
                                      uint32_t addr) {
    asm volatile("ldmatrix.sync.aligned.m8n8.x4.shared.b16 {%0,%1,%2,%3}, [%4];"
                 : "=r"(r0), "=r"(r1), "=r"(r2), "=r"(r3) : "r"(addr));
}
__device__ __forceinline__ void mma16816(float* c, const uint32_t* a, uint32_t b0, uint32_t b1) {
    asm volatile(
        "mma.sync.aligned.m16n8k16.row.col.f32.f16.f16.f32 "
        "{%0,%1,%2,%3}, {%4,%5,%6,%7}, {%8,%9}, {%0,%1,%2,%3};"
        : "+f"(c[0]), "+f"(c[1]), "+f"(c[2]), "+f"(c[3])
        : "r"(a[0]), "r"(a[1]), "r"(a[2]), "r"(a[3]), "r"(b0), "r"(b1));
}

// ---------------- kernel 1: fp16 mma GEMM + fused softmax moments ----------------
// grid (NSTRIP, P), 512 threads / 16 warps.
// Frags of 16 kp: warp w owns frag w; warps 8-15 also own frag w+8; warp 0 also frag 24.
// Staging (warps 0-7): thread owns column m = w*8+(lane&7), k-quarter kg = lane>>3;
// norms via intra-warp shfl (dense read exactly once). One __syncthreads per chunk.
__global__ void __launch_bounds__(NTHREADS, 1)
k_match(const float* __restrict__ dense, const float* __restrict__ kdesc,
        const int* __restrict__ tgt_ids, const int* __restrict__ src_ids) {
    extern __shared__ char sm[];
    const uint32_t sb = (uint32_t)__cvta_generic_to_shared(sm);
    const int tid = threadIdx.x, w = tid >> 5, lane = tid & 31;
    const int strip = blockIdx.x, p = blockIdx.y;
    const int c0 = (strip * NCHUNK_G) / NSTRIP;
    const int c1 = ((strip + 1) * NCHUNK_G) / NSTRIP;
    const float* srcb = dense + (size_t)src_ids[p] * CDIM * HW_;

    const bool is_stage = (w < 8);
    const int mcol = (w & 7) * 8 + (lane & 7);   // column within chunk
    const int kg   = lane >> 3;                  // k-quarter (16 k values)

    // ---- early LDG of chunk c0 (staging warps) ----
    float R[16];
    if (is_stage) {
#pragma unroll
        for (int i = 0; i < 16; ++i)
            R[i] = srcb[(size_t)(kg * 16 + i) * HW_ + (size_t)c0 * CHUNK_M + mcol];
    }

    // ---- build A tile: normalize tgt inline, fold LOGIT_C, single fp16 ----
    if (tid < NKP) {
        const int kp = tid;
        const float* tb = kdesc + (size_t)tgt_ids[p] * CDIM * NKP + kp;
        float v[CDIM];
        float ss = 0.f;
#pragma unroll
        for (int c = 0; c < CDIM; ++c) { v[c] = tb[c * NKP]; ss = fmaf(v[c], v[c], ss); }
        float inv = LOGIT_C / fmaxf(sqrtf(ss), 1e-12f);
#pragma unroll
        for (int kb = 0; kb < CDIM; kb += 8) {
            uint32_t q[4];
#pragma unroll
            for (int j = 0; j < 4; ++j)
                q[j] = pkh2(v[kb + 2 * j] * inv, v[kb + 2 * j + 1] * inv);
            *(uint4*)(sm + SA + kp * 144 + kb * 2) = make_uint4(q[0], q[1], q[2], q[3]);
        }
    }

    // ---- prologue: convert chunk c0 (norm via shfl), prefetch c0+1 ----
    if (is_stage) {
        float ss = 0.f;
#pragma unroll
        for (int i = 0; i < 16; ++i) ss = fmaf(R[i], R[i], ss);
        ss += __shfl_xor_sync(0xffffffffu, ss, 8);
        ss += __shfl_xor_sync(0xffffffffu, ss, 16);
        float inv = 1.0f / fmaxf(sqrtf(ss), 1e-12f);
        char* bb = sm + SB + (c0 & 1) * 9216;
        uint32_t q[8];
#pragma unroll
        for (int j = 0; j < 8; ++j) q[j] = pkh2(R[2 * j] * inv, R[2 * j + 1] * inv);
        *(uint4*)(bb + mcol * 144 + kg * 32)      = make_uint4(q[0], q[1], q[2], q[3]);
        *(uint4*)(bb + mcol * 144 + kg * 32 + 16) = make_uint4(q[4], q[5], q[6], q[7]);
        if (c0 + 1 < c1) {
#pragma unroll
            for (int i = 0; i < 16; ++i)
                R[i] = srcb[(size_t)(kg * 16 + i) * HW_ + (size_t)(c0 + 1) * CHUNK_M + mcol];
        }
    }

    // frag assignment: slot 0 = frag w; slot 1 = w+8 (warps 8-15) or 24 (warp 0)
    const int f1 = (w >= 8) ? (w + 8) : (w == 0 ? 24 : -1);

    // persistent softmax moment accumulators [slot][rowpart]
    float S[2][2]  = {{0.f,0.f},{0.f,0.f}};
    float XO[2][2] = {{0.f,0.f},{0.f,0.f}};
    float XB[2][2] = {{0.f,0.f},{0.f,0.f}};
    float Yc[2][2] = {{0.f,0.f},{0.f,0.f}};

    const int preA = ((lane & 7) + ((lane >> 3) & 1) * 8) * 144 + ((lane >> 4) & 1) * 16;
    const int preB = ((lane & 7) + ((lane >> 4) & 1) * 8) * 144 + ((lane >> 3) & 1) * 16;
    const float xol = (float)((lane & 3) * 2);

    for (int t = c0; t < c1; ++t) {
        __syncthreads();   // buf[t&1] ready; previous chunk's readers of buf[(t+1)&1] done

        // ---- staging first: convert chunk t+1 into buf[(t+1)&1], prefetch t+2 ----
        if (is_stage && t + 1 < c1) {
            float ss = 0.f;
#pragma unroll
            for (int i = 0; i < 16; ++i) ss = fmaf(R[i], R[i], ss);
            ss += __shfl_xor_sync(0xffffffffu, ss, 8);
            ss += __shfl_xor_sync(0xffffffffu, ss, 16);
            float inv = 1.0f / fmaxf(sqrtf(ss), 1e-12f);
            char* bb = sm + SB + ((t + 1) & 1) * 9216;
            uint32_t q[8];
#pragma unroll
            for (int j = 0; j < 8; ++j) q[j] = pkh2(R[2 * j] * inv, R[2 * j + 1] * inv);
            *(uint4*)(bb + mcol * 144 + kg * 32)      = make_uint4(q[0], q[1], q[2], q[3]);
            *(uint4*)(bb + mcol * 144 + kg * 32 + 16) = make_uint4(q[4], q[5], q[6], q[7]);
            if (t + 2 < c1) {
#pragma unroll
                for (int i = 0; i < 16; ++i)
                    R[i] = srcb[(size_t)(kg * 16 + i) * HW_ + (size_t)(t + 2) * CHUNK_M + mcol];
            }
        }

        // ---- compute chunk t ----
        const uint32_t Bb = sb + SB + (t & 1) * 9216;
        const int m0 = t * CHUNK_M;
        const float xb = (float)(m0 & 255), yv = (float)(m0 >> 8);

#pragma unroll
        for (int slot = 0; slot < 2; ++slot) {
            const int f = (slot == 0) ? w : f1;
            if (f < 0) continue;
            const uint32_t Ah = sb + SA + f * 16 * 144 + preA;
            float c[8][4];
#pragma unroll
            for (int ff = 0; ff < 8; ++ff)      // fold -100*log2e into accumulator init
                c[ff][0] = c[ff][1] = c[ff][2] = c[ff][3] = -LOGIT_C;

#pragma unroll
            for (int ks = 0; ks < 4; ++ks) {
                uint32_t ah[4];
                ldsm4(ah[0], ah[1], ah[2], ah[3], Ah + ks * 32);
#pragma unroll
                for (int fp = 0; fp < 4; ++fp) {
                    uint32_t b0, b1, b2, b3;
                    ldsm4(b0, b1, b2, b3, Bb + fp * 2304 + preB + ks * 32);
                    mma16816(c[2 * fp],     ah, b0, b1);
                    mma16816(c[2 * fp + 1], ah, b2, b3);
                }
            }

            // ---- epilogue: w = 2^c; rows = keypoints (in-register moments) ----
            float s0 = S[slot][0], s1 = S[slot][1];
            float x0 = XO[slot][0], x1 = XO[slot][1];
            const float sn0 = s0, sn1 = s1;
#pragma unroll
            for (int ff = 0; ff < 8; ++ff) {
                float xo = xol + (float)(ff * 8);
                float w0 = ex2f(c[ff][0]);
                float w1 = ex2f(c[ff][1]);
                float w2 = ex2f(c[ff][2]);
                float w3 = ex2f(c[ff][3]);
                s0 += w0 + w1;
                x0 = fmaf(w0, xo, x0); x0 = fmaf(w1, xo + 1.f, x0);
                s1 += w2 + w3;
                x1 = fmaf(w2, xo, x1); x1 = fmaf(w3, xo + 1.f, x1);
            }
            S[slot][0] = s0; S[slot][1] = s1; XO[slot][0] = x0; XO[slot][1] = x1;
            XB[slot][0] = fmaf(xb, s0 - sn0, XB[slot][0]);
            XB[slot][1] = fmaf(xb, s1 - sn1, XB[slot][1]);
            Yc[slot][0] = fmaf(yv, s0 - sn0, Yc[slot][0]);
            Yc[slot][1] = fmaf(yv, s1 - sn1, Yc[slot][1]);
        }
    }

    // ---- reduce over the 4 col-lanes and store partials ----
#pragma unroll
    for (int slot = 0; slot < 2; ++slot) {
        const int f = (slot == 0) ? w : f1;
        if (f < 0) continue;
#pragma unroll
        for (int rp = 0; rp < 2; ++rp) {
            float s = S[slot][rp], x = XO[slot][rp] + XB[slot][rp], y = Yc[slot][rp];
            s += __shfl_xor_sync(0xffffffffu, s, 1);
            x += __shfl_xor_sync(0xffffffffu, x, 1);
            y += __shfl_xor_sync(0xffffffffu, y, 1);
            s += __shfl_xor_sync(0xffffffffu, s, 2);
            x += __shfl_xor_sync(0xffffffffu, x, 2);
            y += __shfl_xor_sync(0xffffffffu, y, 2);
            if ((lane & 3) == 0) {
                int kp = f * 16 + (lane >> 2) + 8 * rp;
                g_part4[((size_t)p * NKP + kp) * NSTRIP + strip] = make_float4(s, x, y, 0.f);
            }
        }
    }
}

// ---------------- kernel 2: combine partials + emit scores/ids (4 kp / 128-thr block) ----------------
__global__ void k_combine(const float* __restrict__ kscores,
                          const int* __restrict__ tgt_ids, const int* __restrict__ src_ids,
                          float* __restrict__ out, int P, int out_size) {
    int gw   = blockIdx.x * 4 + (threadIdx.x >> 5);
    int lane = threadIdx.x & 31;
    if (blockIdx.x == 0 && threadIdx.x == 0) {
        int base = P * NKP * 3;
        for (int pp = 0; pp < P; ++pp) {
            if (base + pp < out_size)     out[base + pp]     = (float)tgt_ids[pp];
            if (base + P + pp < out_size) out[base + P + pp] = (float)src_ids[pp];
        }
    }
    if (gw >= P * NKP) return;
    int p = gw / NKP, kp = gw - p * NKP;
    const float4* base = &g_part4[((size_t)p * NKP + kp) * NSTRIP];
    float4 v0 = base[lane];
    float4 v1 = base[lane + 32];                 // 32..63 < 74 always
    float4 v2 = (lane + 64 < NSTRIP) ? base[lane + 64] : make_float4(0.f, 0.f, 0.f, 0.f);
    float S = v0.x + v1.x + v2.x;
    float X = v0.y + v1.y + v2.y;
    float Y = v0.z + v1.z + v2.z;
#pragma unroll
    for (int off = 16; off; off >>= 1) {
        S += __shfl_xor_sync(0xffffffffu, S, off);
        X += __shfl_xor_sync(0xffffffffu, X, off);
        Y += __shfl_xor_sync(0xffffffffu, Y, off);
    }
    if (lane == 0) {
        if (gw * 2 + 1 < out_size) {
            out[gw * 2 + 0] = X / S;
            out[gw * 2 + 1] = Y / S;
        }
        int so = P * NKP * 2 + p * NKP + kp;
        if (so < out_size) out[so] = kscores[tgt_ids[p] * NKP + kp];
    }
}

// ---------------- launch ----------------
extern "C" void kernel_launch(void* const* d_in, const int* in_sizes, int n_in,
                              void* d_out, int out_size) {
    const float* kscores = (const float*)d_in[0];
    const float* kdesc   = (const float*)d_in[1];
    const float* dense   = (const float*)d_in[2];
    const int*   tgt_ids = (const int*)d_in[3];
    const int*   src_ids = (const int*)d_in[4];
    int P = in_sizes[3];
    if (P > PMAX) P = PMAX;
    float* out = (float*)d_out;

    cudaFuncSetAttribute(k_match, cudaFuncAttributeMaxDynamicSharedMemorySize, SMEMSZ);
    k_match<<<dim3(NSTRIP, P), NTHREADS, SMEMSZ>>>(dense, kdesc, tgt_ids, src_ids);

    k_combine<<<(P * NKP + 3) / 4, 128>>>(kscores, tgt_ids, src_ids, out, P, out_size);
}